// round 11
// baseline (speedup 1.0000x reference)
#include <cuda_runtime.h>
#include <cstdint>
#include <cstddef>
#include <math.h>

// Problem constants (fixed by the reference: B=8, N=4096, NITER=4)
constexpr int B = 8;
constexpr int N = 4096;
constexpr int NITER = 4;
constexpr int BN = B * N;

constexpr int NCHUNK = 32;            // b-dimension split
constexpr int CB = N / NCHUNK;        // 128 P-rows per chunk
constexpr int TILE_A = 128;           // output columns per block
constexpr int NTILE = N / TILE_A;     // 32 a-tiles
constexpr int BLOCK_T = 128;          // threads per block
constexpr int GRID = NTILE * NCHUNK;  // 1024 blocks — all co-resident (<= 148*8)
constexpr int OUT_PER_BLK = BN / GRID;  // 32 outputs per block in combine phase

// Static scratch (no allocations allowed)
__device__ float g_part[(size_t)NCHUNK * BN];   // 4 MB partial sums
__device__ float g_pred[BN];                    // current pred between iterations
__device__ unsigned g_arrive = 0;               // monotonic arrive counter
__device__ unsigned g_release = 0;              // monotonic release counter

using ull = unsigned long long;

__device__ __forceinline__ ull pk2(float x) {
    ull r; asm("mov.b64 %0, {%1, %1};" : "=l"(r) : "f"(x)); return r;
}
__device__ __forceinline__ ull fma2(ull a, ull b, ull c) {
    ull d; asm("fma.rn.f32x2 %0, %1, %2, %3;" : "=l"(d) : "l"(a), "l"(b), "l"(c)); return d;
}
__device__ __forceinline__ void upk2(ull v, float& lo, float& hi) {
    asm("mov.b64 {%0, %1}, %2;" : "=f"(lo), "=f"(hi) : "l"(v));
}

// Grid-wide barrier. Counters are monotonic across launches/replays (never reset);
// rbase = g_release sampled at kernel start. The sample is race-free: the first
// release increment of THIS launch can only happen after all GRID blocks arrived
// at barrier 0, i.e. after every block has already sampled.
__device__ __forceinline__ void grid_bar(unsigned rbase, int& j) {
    __threadfence();     // drain this thread's global stores (release side)
    __syncthreads();
    if (threadIdx.x == 0) {
        unsigned old = atomicAdd(&g_arrive, 1u);
        if (old == (rbase + (unsigned)j) * (unsigned)GRID + (unsigned)(GRID - 1)) {
            atomicAdd(&g_release, 1u);
        } else {
            unsigned tgt = rbase + (unsigned)j + 1u;
            while ((int)(*(volatile unsigned*)&g_release - tgt) < 0) __nanosleep(128);
        }
    }
    __syncthreads();
    j++;
}

// One launch runs all NITER iterations.
// Phase 1 (block = (tile, chunk)): partial sums S_c[i,a] = sum_{b in chunk} pred[i,b]*P[b,a].
//   Thread (q,p): 4 consecutive a-columns, batch pair p; warp-dedup P float4 loads.
// Phase 2 (ALL blocks): block handles 32 consecutive flat outputs; warp w sums
//   chunks [8w,8w+8) for 32 outputs; cross-warp reduce in smem; warp 0 applies
//   1-exp(-S), seed clamp, writes g_pred (+ d_out on last iteration).
__global__ void __launch_bounds__(BLOCK_T, 8) prop_all(
    const float* __restrict__ P, const float* __restrict__ pred0,
    const int2* __restrict__ seed, int nseeds, float* __restrict__ out)
{
    __shared__ ull s_p2[CB * 4];      // pred chunk, batch-paired (4 KB)
    __shared__ float s_sum[BLOCK_T];
    __shared__ int s_flat[128];
    __shared__ unsigned s_rb;
    float* s_f = reinterpret_cast<float*>(s_p2);

    const int tid = threadIdx.x;
    const int bid = blockIdx.x;
    const int tile = bid & (NTILE - 1);
    const int chunk = bid >> 5;
    const int b0 = chunk * CB;

    if (tid == 0) s_rb = *(volatile unsigned*)&g_release;
    if (tid < 128) s_flat[tid] = (tid < nseeds) ? (seed[tid].x * N + seed[tid].y) : -1;
    __syncthreads();
    const unsigned rbase = s_rb;
    int bar = 0;

    const int q = tid >> 2;          // col quad 0..31
    const int p = tid & 3;           // batch pair 0..3
    const int a0 = tile * TILE_A + q * 4;
    const float4* __restrict__ p4 =
        reinterpret_cast<const float4*>(P + (size_t)b0 * N) + (a0 >> 2);
    const int w = tid >> 5, k = tid & 31;
    const int o0 = bid * OUT_PER_BLK;

    for (int t = 0; t < NITER; t++) {
        // ---- Phase 1: stage pred chunk into smem (L2-coherent reads) ----
        {
            const float* __restrict__ pred = (t == 0) ? pred0 : g_pred;
#pragma unroll
            for (int j = 0; j < (CB * B) / BLOCK_T; j++) {   // 8 per thread
                int idx = j * BLOCK_T + tid;
                int i = idx >> 7;          // batch 0..7
                int b = idx & (CB - 1);    // local row 0..127
                s_f[b * 8 + i] = __ldcg(&pred[i * N + b0 + b]);
            }
        }
        __syncthreads();

        ull acc0 = 0, acc1 = 0, acc2 = 0, acc3 = 0;
#pragma unroll 8
        for (int b = 0; b < CB; b++) {
            float4 pv = __ldg(&p4[(size_t)b * (N >> 2)]);
            ull np = s_p2[b * 4 + p];
            acc0 = fma2(pk2(pv.x), np, acc0);
            acc1 = fma2(pk2(pv.y), np, acc1);
            acc2 = fma2(pk2(pv.z), np, acc2);
            acc3 = fma2(pk2(pv.w), np, acc3);
        }

        {
            float lo0, hi0, lo1, hi1, lo2, hi2, lo3, hi3;
            upk2(acc0, lo0, hi0); upk2(acc1, lo1, hi1);
            upk2(acc2, lo2, hi2); upk2(acc3, lo3, hi3);
            float* outc = g_part + (size_t)chunk * BN;
            __stcg(reinterpret_cast<float4*>(outc + (size_t)(2 * p) * N + a0),
                   make_float4(lo0, lo1, lo2, lo3));
            __stcg(reinterpret_cast<float4*>(outc + (size_t)(2 * p + 1) * N + a0),
                   make_float4(hi0, hi1, hi2, hi3));
        }

        grid_bar(rbase, bar);   // partials visible chip-wide

        // ---- Phase 2: distributed combine ----
        {
            const float* __restrict__ pl = g_part + (size_t)(w * 8) * BN + o0 + k;
            float a0s = __ldcg(pl + 0 * (size_t)BN);
            float a1s = __ldcg(pl + 1 * (size_t)BN);
            float a2s = __ldcg(pl + 2 * (size_t)BN);
            float a3s = __ldcg(pl + 3 * (size_t)BN);
            float a4s = __ldcg(pl + 4 * (size_t)BN);
            float a5s = __ldcg(pl + 5 * (size_t)BN);
            float a6s = __ldcg(pl + 6 * (size_t)BN);
            float a7s = __ldcg(pl + 7 * (size_t)BN);
            s_sum[tid] = ((a0s + a1s) + (a2s + a3s)) + ((a4s + a5s) + (a6s + a7s));
        }
        __syncthreads();
        if (w == 0) {
            float v = (s_sum[k] + s_sum[32 + k]) + (s_sum[64 + k] + s_sum[96 + k]);
            v = 1.0f - __expf(-v);
            int o = o0 + k;
            for (int s = 0; s < nseeds; s++)
                if (s_flat[s] == o) v = 1.0f;
            __stcg(&g_pred[o], v);
            if (t == NITER - 1) out[o] = v;
        }

        if (t != NITER - 1)
            grid_bar(rbase, bar);   // pred visible before next phase 1
    }
}

extern "C" void kernel_launch(void* const* d_in, const int* in_sizes, int n_in,
                              void* d_out, int out_size) {
    const float* preds = (const float*)d_in[0];      // [B, N] fp32
    const float* P = (const float*)d_in[1];          // [N, N] fp32, P[b*N + a]
    const int2* seed = (const int2*)d_in[2];         // [NSEEDS, 2] int32 (b, n)
    int nseeds = in_sizes[2] / 2;
    if (nseeds > 128) nseeds = 128;
    float* out = (float*)d_out;

    prop_all<<<GRID, BLOCK_T>>>(P, preds, seed, nseeds, out);
}